// round 10
// baseline (speedup 1.0000x reference)
#include <cuda_runtime.h>
#include <cstdint>

#define NB 16
#define NT 2048
#define ND 512
#define TBLK 8             // timesteps per alphas block
#define CH 32              // pass-2 chunk length (timesteps)
#define NCH (NT / CH)      // 64 chunks
#define GR 8               // ranks per gather block

// ---------------- scratch (device globals; no allocation allowed) ----------
__device__ __align__(16) float g_aT4[NT * NB];   // alphas, layout [t/4][b][4]
__device__ __align__(16) float g_Wt[NB * NT];    // per-step weight (cur), exact
__device__ __align__(16) float2 g_fire[NB * NT]; // per fire: (t as int bits, rem)
__device__ float g_integ0[NCH * NB];             // integ at chunk start
__device__ int   g_nf0[NCH * NB];                // fire count before chunk
__device__ int   g_nf[NB];                       // total fire count per batch

// set.ge.f32 -> 1.0f/0.0f without a predicate on the dependency chain
__device__ __forceinline__ float fset_ge1(float s) {
    float r;
    asm("set.ge.f32.f32 %0, %1, 0f3F800000;" : "=f"(r) : "f"(s));
    return r;
}

__device__ __forceinline__ uint32_t smem_u32(const void* p) {
    uint32_t a;
    asm("{ .reg .u64 t; cvta.to.shared.u64 t, %1; cvt.u32.u64 %0, t; }"
        : "=r"(a) : "l"(p));
    return a;
}

__device__ __forceinline__ void mbar_wait0(uint32_t mbar) {
    asm volatile(
        "{\n\t.reg .pred P1;\n\t"
        "W%=:\n\t"
        "mbarrier.try_wait.parity.acquire.cta.shared::cta.b64 P1, [%0], 0, 0x989680;\n\t"
        "@!P1 bra W%=;\n\t}"
        :: "r"(mbar) : "memory");
}

// ---------------- kernel A: alphas, small-tile TMA, occupancy 8 -------------
// (r9-proven) Block = 128 threads covers 8 consecutive t of one batch; rows
// t0-1..t0+8 (10 rows, 20KB smem) arrive via ONE cp.async.bulk; 8 CTAs/SM.
__global__ __launch_bounds__(128, 8)
void alphas_kernel(const float* __restrict__ hidden,
                   const float* __restrict__ conv_w,
                   const float* __restrict__ conv_b,
                   const float* __restrict__ lin_w,
                   const float* __restrict__ lin_b,
                   float* __restrict__ alphas) {
    __shared__ __align__(128) float sh[(TBLK + 2) * ND];   // 20KB
    __shared__ __align__(8) unsigned long long mbar;

    const int b  = blockIdx.y;
    const int t0 = blockIdx.x * TBLK;

    const int gstart = (t0 == 0) ? 0 : t0 - 1;
    const int gend   = (t0 + TBLK < NT) ? t0 + TBLK : NT - 1;
    const int nrows  = gend - gstart + 1;           // 9 or 10
    const int dstrow = (t0 == 0) ? 1 : 0;

    if (t0 == 0) {                                  // zero pad row 0
        for (int q = threadIdx.x; q < ND / 4; q += 128)
            reinterpret_cast<float4*>(sh)[q] = make_float4(0.f, 0.f, 0.f, 0.f);
    } else if (t0 + TBLK == NT) {                   // zero pad row 9
        for (int q = threadIdx.x; q < ND / 4; q += 128)
            reinterpret_cast<float4*>(sh + (TBLK + 1) * ND)[q] =
                make_float4(0.f, 0.f, 0.f, 0.f);
    }

    const uint32_t mb = smem_u32(&mbar);
    if (threadIdx.x == 0) {
        asm volatile("mbarrier.init.shared.b64 [%0], 1;" :: "r"(mb) : "memory");
    }
    __syncthreads();
    if (threadIdx.x == 0) {
        const uint32_t bytes = nrows * ND * 4;
        const uint32_t dst   = smem_u32(sh) + dstrow * ND * 4;
        const float* src = hidden + (size_t)b * NT * ND + (size_t)gstart * ND;
        asm volatile("mbarrier.arrive.expect_tx.shared.b64 _, [%0], %1;"
                     :: "r"(mb), "r"(bytes) : "memory");
        asm volatile(
            "cp.async.bulk.shared::cta.global.mbarrier::complete_tx::bytes "
            "[%0], [%1], %2, [%3];"
            :: "r"(dst), "l"(src), "r"(bytes), "r"(mb) : "memory");
    }
    mbar_wait0(mb);

    const int warp = threadIdx.x >> 5;      // 0..3
    const int lane = threadIdx.x & 31;
    const int tl   = warp * 2;              // local t (0..6), rows tl..tl+3

    float acc0 = 0.f, acc1 = 0.f;

#pragma unroll 2
    for (int j = 0; j < 4; j++) {
        const int d = lane * 4 + j * 128;
        const float4 c0 = *reinterpret_cast<const float4*>(&conv_w[d * 3]);
        const float4 c1 = *reinterpret_cast<const float4*>(&conv_w[d * 3 + 4]);
        const float4 c2 = *reinterpret_cast<const float4*>(&conv_w[d * 3 + 8]);
        const float4 w0 = make_float4(c0.x, c0.w, c1.z, c2.y);
        const float4 w1 = make_float4(c0.y + 1.f, c1.x + 1.f, c1.w + 1.f, c2.z + 1.f);
        const float4 w2 = make_float4(c0.z, c1.y, c2.x, c2.w);
        const float4 cb4 = *reinterpret_cast<const float4*>(&conv_b[d]);
        const float4 lw  = *reinterpret_cast<const float4*>(&lin_w[d]);

        const float4 r0 = *reinterpret_cast<const float4*>(&sh[(tl + 0) * ND + d]);
        const float4 r1 = *reinterpret_cast<const float4*>(&sh[(tl + 1) * ND + d]);
        const float4 r2 = *reinterpret_cast<const float4*>(&sh[(tl + 2) * ND + d]);
        const float4 r3 = *reinterpret_cast<const float4*>(&sh[(tl + 3) * ND + d]);

        float v;
        v = fmaf(r0.x, w0.x, fmaf(r1.x, w1.x, fmaf(r2.x, w2.x, cb4.x)));
        acc0 = fmaf(fmaxf(v, 0.f), lw.x, acc0);
        v = fmaf(r0.y, w0.y, fmaf(r1.y, w1.y, fmaf(r2.y, w2.y, cb4.y)));
        acc0 = fmaf(fmaxf(v, 0.f), lw.y, acc0);
        v = fmaf(r0.z, w0.z, fmaf(r1.z, w1.z, fmaf(r2.z, w2.z, cb4.z)));
        acc0 = fmaf(fmaxf(v, 0.f), lw.z, acc0);
        v = fmaf(r0.w, w0.w, fmaf(r1.w, w1.w, fmaf(r2.w, w2.w, cb4.w)));
        acc0 = fmaf(fmaxf(v, 0.f), lw.w, acc0);

        v = fmaf(r1.x, w0.x, fmaf(r2.x, w1.x, fmaf(r3.x, w2.x, cb4.x)));
        acc1 = fmaf(fmaxf(v, 0.f), lw.x, acc1);
        v = fmaf(r1.y, w0.y, fmaf(r2.y, w1.y, fmaf(r3.y, w2.y, cb4.y)));
        acc1 = fmaf(fmaxf(v, 0.f), lw.y, acc1);
        v = fmaf(r1.z, w0.z, fmaf(r2.z, w1.z, fmaf(r3.z, w2.z, cb4.z)));
        acc1 = fmaf(fmaxf(v, 0.f), lw.z, acc1);
        v = fmaf(r1.w, w0.w, fmaf(r2.w, w1.w, fmaf(r3.w, w2.w, cb4.w)));
        acc1 = fmaf(fmaxf(v, 0.f), lw.w, acc1);
    }

#pragma unroll
    for (int o = 16; o > 0; o >>= 1) {
        acc0 += __shfl_xor_sync(0xffffffffu, acc0, o);
        acc1 += __shfl_xor_sync(0xffffffffu, acc1, o);
    }
    if (lane == 0) {
        const float lb = __ldg(lin_b);
        const int t = t0 + tl;
        const float2 av = make_float2(1.0f / (1.0f + __expf(-(acc0 + lb))),
                                      1.0f / (1.0f + __expf(-(acc1 + lb))));
        *reinterpret_cast<float2*>(&alphas[b * NT + t]) = av;
        *reinterpret_cast<float2*>(&g_aT4[((t >> 2) * NB + b) * 4 + (t & 3)]) = av;
    }
}

// ---------------- kernel B1: minimal sequential chain (pass 1) -------------
// (r7-proven) Chain: FADD -> FSET (predicate-free) -> FADD = 12 cyc/step.
__global__ void scan_pass1(float* __restrict__ token_num) {
    const int b = threadIdx.x;
    if (b >= NB) return;

    const float4* ap = reinterpret_cast<const float4*>(g_aT4) + b;
    float4 buf_cur[8], buf_nxt[8];
#pragma unroll
    for (int k = 0; k < 8; k++) buf_cur[k] = ap[k * NB];

    float integ = 0.f, tn = 0.f, nfF = 0.f;

    for (int t0 = 0; t0 < NT; t0 += CH) {
        g_integ0[(t0 >> 5) * NB + b] = integ;
        g_nf0[(t0 >> 5) * NB + b]   = (int)nfF;
        if (t0 + CH < NT) {
#pragma unroll
            for (int k = 0; k < 8; k++) buf_nxt[k] = ap[((t0 >> 2) + 8 + k) * NB];
        }
#pragma unroll
        for (int k = 0; k < 8; k++) {
            float a4[4] = {buf_cur[k].x, buf_cur[k].y, buf_cur[k].z, buf_cur[k].w};
#pragma unroll
            for (int i = 0; i < 4; i++) {
                const float a   = a4[i];
                const float s   = integ + a;
                const float sel = fset_ge1(s);
                nfF += sel;
                tn  += a;
                integ = s - sel;
            }
        }
#pragma unroll
        for (int k = 0; k < 8; k++) buf_cur[k] = buf_nxt[k];
    }
    g_nf[b] = (int)nfF;
    token_num[b] = tn;
}

// ---------------- kernel B2: parallel chunk replay (pass 2) ----------------
__global__ void scan_pass2(float* __restrict__ fires) {
    const int c = blockIdx.x;
    const int b = threadIdx.x;
    if (b >= NB) return;

    float integ = g_integ0[c * NB + b];
    int nf      = g_nf0[c * NB + b];
    const int tbase = c * CH;
    const float4* ap = reinterpret_cast<const float4*>(g_aT4) + b;
    float*  fb = fires + b * NT;
    float*  wb = g_Wt + b * NT;
    float2* pb = g_fire + b * NT;

#pragma unroll
    for (int k = 0; k < 8; k++) {
        const float4 av = ap[((tbase >> 2) + k) * NB];
        float a4[4] = {av.x, av.y, av.z, av.w};
        float4 fout, wout;
#pragma unroll
        for (int i = 0; i < 4; i++) {
            const float a    = a4[i];
            const float dist = 1.0f - integ;
            const float s    = integ + a;
            const bool fire  = (s >= 1.0f);
            const float cur  = fire ? dist : a;
            ((float*)&fout)[i] = s;
            ((float*)&wout)[i] = cur;
            const float rem = a - cur;
            if (fire) pb[nf] = make_float2(__int_as_float(tbase + k * 4 + i), rem);
            nf += fire ? 1 : 0;
            integ = fire ? (s - 1.0f) : s;
        }
        const int t = tbase + k * 4;
        *reinterpret_cast<float4*>(fb + t) = fout;
        *reinterpret_cast<float4*>(wb + t) = wout;
    }
}

// ---------------- kernel C: rank-group streaming gather --------------------
// Block per (b, group of GR ranks): the union of GR consecutive segments is a
// CONTIGUOUS t-range. Stream it once; at each fire boundary store the rank's
// accumulator and seed the next rank with rem * lasth (fire row reused from
// registers — never reloaded). Loads: whole 2KB rows back-to-back, high MLP.
// Per-output arithmetic identical to r9 (seed multiply, ascending-t fma).
__global__ __launch_bounds__(128)
void gather_kernel(const float* __restrict__ hidden,
                   float* __restrict__ acoustic, int ML) {
    const int b  = blockIdx.y;
    const int r0 = blockIdx.x * GR;
    const int d  = threadIdx.x * 4;
    const int nf = g_nf[b];

    const float*  hb = hidden + (size_t)b * NT * ND + d;
    const float2* fr = g_fire + b * NT;
    const float*  wb = g_Wt + b * NT;
    float* ob = acoustic + ((size_t)b * ML + r0) * ND + d;

    float4 acc = make_float4(0.f, 0.f, 0.f, 0.f);
    int start = 0;
    if (r0 > 0 && r0 - 1 < nf) {                    // seed from previous fire
        const float2 fp = fr[r0 - 1];
        const int ps    = __float_as_int(fp.x);
        const float4 h  = *reinterpret_cast<const float4*>(hb + (size_t)ps * ND);
        acc.x = fp.y * h.x; acc.y = fp.y * h.y;
        acc.z = fp.y * h.z; acc.w = fp.y * h.w;
        start = ps + 1;
    }

#pragma unroll 1
    for (int g = 0; g < GR; g++) {
        const int r = r0 + g;
        if (r >= ML) break;
        if (r < nf) {
            const float2 fc = fr[r];
            const int end   = __float_as_int(fc.x);
            float4 lasth;
#pragma unroll 2
            for (int t = start; t <= end; t++) {
                const float w  = wb[t];              // uniform broadcast (exact cur)
                const float4 h = *reinterpret_cast<const float4*>(hb + (size_t)t * ND);
                acc.x = fmaf(w, h.x, acc.x); acc.y = fmaf(w, h.y, acc.y);
                acc.z = fmaf(w, h.z, acc.z); acc.w = fmaf(w, h.w, acc.w);
                lasth = h;
            }
            *reinterpret_cast<float4*>(ob + (size_t)g * ND) = acc;
            // seed next rank: rem * fire-row (segment always contains >= 1 row)
            acc.x = fc.y * lasth.x; acc.y = fc.y * lasth.y;
            acc.z = fc.y * lasth.z; acc.w = fc.y * lasth.w;
            start = end + 1;
        } else {
            // r >= nf: zero padding (also overwrites 0xAA poison)
            *reinterpret_cast<float4*>(ob + (size_t)g * ND) =
                make_float4(0.f, 0.f, 0.f, 0.f);
        }
    }
}

// ---------------- launch ----------------------------------------------------
extern "C" void kernel_launch(void* const* d_in, const int* in_sizes, int n_in,
                              void* d_out, int out_size) {
    const float* hidden = (const float*)d_in[0];
    const float* conv_w = (const float*)d_in[1];
    const float* conv_b = (const float*)d_in[2];
    const float* lin_w  = (const float*)d_in[3];
    const float* lin_b  = (const float*)d_in[4];
    float* out = (float*)d_out;

    // out = concat(acoustic[B,ML,D], token_num[B], alphas[B,T], fires[B,T])
    const int ML = (out_size - NB - 2 * NB * NT) / (NB * ND);
    float* acoustic  = out;
    float* token_num = out + (size_t)NB * ML * ND;
    float* alphas    = token_num + NB;
    float* fires     = alphas + NB * NT;

    alphas_kernel<<<dim3(NT / TBLK, NB), 128>>>(hidden, conv_w, conv_b,
                                                lin_w, lin_b, alphas);
    scan_pass1<<<1, 32>>>(token_num);
    scan_pass2<<<NCH, 32>>>(fires);
    if (ML > 0)
        gather_kernel<<<dim3((ML + GR - 1) / GR, NB), 128>>>(hidden, acoustic, ML);
}

// round 11
// speedup vs baseline: 1.1486x; 1.1486x over previous
#include <cuda_runtime.h>
#include <cstdint>

#define NB 16
#define NT 2048
#define ND 512
#define TBLK 8             // timesteps per alphas block
#define CH 32              // pass-2 chunk length (timesteps)
#define NCH (NT / CH)      // 64 chunks

// ---------------- scratch (device globals; no allocation allowed) ----------
__device__ __align__(16) float g_aT4[NT * NB];   // alphas, layout [t/4][b][4]
__device__ __align__(16) float g_Wt[NB * NT];    // per-step weight (cur), exact
__device__ __align__(16) float2 g_fire[NB * NT]; // per fire: (t as int bits, rem)
__device__ float g_integ0[NCH * NB];             // integ at chunk start
__device__ int   g_nf0[NCH * NB];                // fire count before chunk
__device__ int   g_nf[NB];                       // total fire count per batch

// set.ge.f32 -> 1.0f/0.0f without a predicate on the dependency chain
__device__ __forceinline__ float fset_ge1(float s) {
    float r;
    asm("set.ge.f32.f32 %0, %1, 0f3F800000;" : "=f"(r) : "f"(s));
    return r;
}

__device__ __forceinline__ uint32_t smem_u32(const void* p) {
    uint32_t a;
    asm("{ .reg .u64 t; cvta.to.shared.u64 t, %1; cvt.u32.u64 %0, t; }"
        : "=r"(a) : "l"(p));
    return a;
}

__device__ __forceinline__ void mbar_wait0(uint32_t mbar) {
    asm volatile(
        "{\n\t.reg .pred P1;\n\t"
        "W%=:\n\t"
        "mbarrier.try_wait.parity.acquire.cta.shared::cta.b64 P1, [%0], 0, 0x989680;\n\t"
        "@!P1 bra W%=;\n\t}"
        :: "r"(mbar) : "memory");
}

// ---------------- kernel A: alphas, one-j layout, weights under TMA ---------
// 128 threads cover 8 consecutive t of one batch; thread handles the FIXED
// d-slice d = tid*4 for all 8 t (128*4 = 512 = ND). TMA fills rows t0-1..t0+8
// (20KB smem); the 5 float4 weight vectors per thread load WHILE the TMA is
// in flight (before the mbarrier wait). Compute rolls hm/hc/hp from smem
// (10 LDS.128/thread). Reduction: in-warp butterfly + 4x8 smem combine.
__global__ __launch_bounds__(128, 8)
void alphas_kernel(const float* __restrict__ hidden,
                   const float* __restrict__ conv_w,
                   const float* __restrict__ conv_b,
                   const float* __restrict__ lin_w,
                   const float* __restrict__ lin_b,
                   float* __restrict__ alphas) {
    __shared__ __align__(128) float sh[(TBLK + 2) * ND];   // 20KB
    __shared__ __align__(8) unsigned long long mbar;
    __shared__ float red[4][TBLK];

    const int b  = blockIdx.y;
    const int t0 = blockIdx.x * TBLK;

    const int gstart = (t0 == 0) ? 0 : t0 - 1;
    const int gend   = (t0 + TBLK < NT) ? t0 + TBLK : NT - 1;
    const int nrows  = gend - gstart + 1;           // 9 or 10
    const int dstrow = (t0 == 0) ? 1 : 0;

    // issue TMA as early as possible (only thread 0 touches mbar until sync)
    const uint32_t mb = smem_u32(&mbar);
    if (threadIdx.x == 0) {
        asm volatile("mbarrier.init.shared.b64 [%0], 1;" :: "r"(mb) : "memory");
        const uint32_t bytes = nrows * ND * 4;
        const uint32_t dst   = smem_u32(sh) + dstrow * ND * 4;
        const float* src = hidden + (size_t)b * NT * ND + (size_t)gstart * ND;
        asm volatile("mbarrier.arrive.expect_tx.shared.b64 _, [%0], %1;"
                     :: "r"(mb), "r"(bytes) : "memory");
        asm volatile(
            "cp.async.bulk.shared::cta.global.mbarrier::complete_tx::bytes "
            "[%0], [%1], %2, [%3];"
            :: "r"(dst), "l"(src), "r"(bytes), "r"(mb) : "memory");
    }

    // weight preload — overlaps the TMA flight (independent of smem tile)
    const int d = threadIdx.x * 4;
    const float4 c0 = *reinterpret_cast<const float4*>(&conv_w[d * 3]);
    const float4 c1 = *reinterpret_cast<const float4*>(&conv_w[d * 3 + 4]);
    const float4 c2 = *reinterpret_cast<const float4*>(&conv_w[d * 3 + 8]);
    const float4 w0 = make_float4(c0.x, c0.w, c1.z, c2.y);
    const float4 w1 = make_float4(c0.y + 1.f, c1.x + 1.f, c1.w + 1.f, c2.z + 1.f);
    const float4 w2 = make_float4(c0.z, c1.y, c2.x, c2.w);
    const float4 cb4 = *reinterpret_cast<const float4*>(&conv_b[d]);
    const float4 lw  = *reinterpret_cast<const float4*>(&lin_w[d]);
    const float lb   = __ldg(lin_b);

    // pad rows (rows the TMA does not write) — also overlaps the flight
    if (t0 == 0) {
        *reinterpret_cast<float4*>(&sh[d]) = make_float4(0.f, 0.f, 0.f, 0.f);
    } else if (t0 + TBLK == NT) {
        *reinterpret_cast<float4*>(&sh[(TBLK + 1) * ND + d]) =
            make_float4(0.f, 0.f, 0.f, 0.f);
    }

    __syncthreads();        // publish mbar init (and pad rows)
    mbar_wait0(mb);

    // rolling 3-tap window over 8 timesteps, fixed d-slice
    float acc[TBLK];
    float4 hm = *reinterpret_cast<const float4*>(&sh[d]);
    float4 hc = *reinterpret_cast<const float4*>(&sh[ND + d]);
#pragma unroll
    for (int i = 0; i < TBLK; i++) {
        const float4 hp = *reinterpret_cast<const float4*>(&sh[(i + 2) * ND + d]);
        float a = 0.f, v;
        v = fmaf(hm.x, w0.x, fmaf(hc.x, w1.x, fmaf(hp.x, w2.x, cb4.x)));
        a = fmaf(fmaxf(v, 0.f), lw.x, a);
        v = fmaf(hm.y, w0.y, fmaf(hc.y, w1.y, fmaf(hp.y, w2.y, cb4.y)));
        a = fmaf(fmaxf(v, 0.f), lw.y, a);
        v = fmaf(hm.z, w0.z, fmaf(hc.z, w1.z, fmaf(hp.z, w2.z, cb4.z)));
        a = fmaf(fmaxf(v, 0.f), lw.z, a);
        v = fmaf(hm.w, w0.w, fmaf(hc.w, w1.w, fmaf(hp.w, w2.w, cb4.w)));
        a = fmaf(fmaxf(v, 0.f), lw.w, a);
        acc[i] = a;
        hm = hc; hc = hp;
    }

    // in-warp butterfly (8 independent chains pipeline the SHFL latency)
#pragma unroll
    for (int o = 16; o > 0; o >>= 1) {
#pragma unroll
        for (int i = 0; i < TBLK; i++)
            acc[i] += __shfl_xor_sync(0xffffffffu, acc[i], o);
    }
    const int warp = threadIdx.x >> 5;
    if ((threadIdx.x & 31) == 0) {
#pragma unroll
        for (int i = 0; i < TBLK; i++) red[warp][i] = acc[i];
    }
    __syncthreads();

    if (threadIdx.x < TBLK) {
        const int i = threadIdx.x;
        const float s = ((red[0][i] + red[1][i]) + (red[2][i] + red[3][i])) + lb;
        const float sg = 1.0f / (1.0f + __expf(-s));
        const int t = t0 + i;
        alphas[b * NT + t] = sg;
        g_aT4[((t >> 2) * NB + b) * 4 + (t & 3)] = sg;
    }
}

// ---------------- kernel B1: minimal sequential chain (pass 1) -------------
// (r7-proven) Chain: FADD -> FSET (predicate-free) -> FADD = 12 cyc/step.
__global__ void scan_pass1(float* __restrict__ token_num) {
    const int b = threadIdx.x;
    if (b >= NB) return;

    const float4* ap = reinterpret_cast<const float4*>(g_aT4) + b;
    float4 buf_cur[8], buf_nxt[8];
#pragma unroll
    for (int k = 0; k < 8; k++) buf_cur[k] = ap[k * NB];

    float integ = 0.f, tn = 0.f, nfF = 0.f;

    for (int t0 = 0; t0 < NT; t0 += CH) {
        g_integ0[(t0 >> 5) * NB + b] = integ;
        g_nf0[(t0 >> 5) * NB + b]   = (int)nfF;
        if (t0 + CH < NT) {
#pragma unroll
            for (int k = 0; k < 8; k++) buf_nxt[k] = ap[((t0 >> 2) + 8 + k) * NB];
        }
#pragma unroll
        for (int k = 0; k < 8; k++) {
            float a4[4] = {buf_cur[k].x, buf_cur[k].y, buf_cur[k].z, buf_cur[k].w};
#pragma unroll
            for (int i = 0; i < 4; i++) {
                const float a   = a4[i];
                const float s   = integ + a;
                const float sel = fset_ge1(s);
                nfF += sel;
                tn  += a;
                integ = s - sel;
            }
        }
#pragma unroll
        for (int k = 0; k < 8; k++) buf_cur[k] = buf_nxt[k];
    }
    g_nf[b] = (int)nfF;
    token_num[b] = tn;
}

// ---------------- kernel B2: parallel chunk replay (pass 2) ----------------
__global__ void scan_pass2(float* __restrict__ fires) {
    const int c = blockIdx.x;
    const int b = threadIdx.x;
    if (b >= NB) return;

    float integ = g_integ0[c * NB + b];
    int nf      = g_nf0[c * NB + b];
    const int tbase = c * CH;
    const float4* ap = reinterpret_cast<const float4*>(g_aT4) + b;
    float*  fb = fires + b * NT;
    float*  wb = g_Wt + b * NT;
    float2* pb = g_fire + b * NT;

#pragma unroll
    for (int k = 0; k < 8; k++) {
        const float4 av = ap[((tbase >> 2) + k) * NB];
        float a4[4] = {av.x, av.y, av.z, av.w};
        float4 fout, wout;
#pragma unroll
        for (int i = 0; i < 4; i++) {
            const float a    = a4[i];
            const float dist = 1.0f - integ;
            const float s    = integ + a;
            const bool fire  = (s >= 1.0f);
            const float cur  = fire ? dist : a;
            ((float*)&fout)[i] = s;
            ((float*)&wout)[i] = cur;
            const float rem = a - cur;
            if (fire) pb[nf] = make_float2(__int_as_float(tbase + k * 4 + i), rem);
            nf += fire ? 1 : 0;
            integ = fire ? (s - 1.0f) : s;
        }
        const int t = tbase + k * 4;
        *reinterpret_cast<float4*>(fb + t) = fout;
        *reinterpret_cast<float4*>(wb + t) = wout;
    }
}

// ---------------- kernel C: parallel segmented gather (r9-proven) ----------
// acoustic[b,r,:] = rem(prev_fire)*h[prev_fire] + sum_{t in (prev,cur]} w_t*h_t
__global__ void gather_kernel(const float* __restrict__ hidden,
                              float* __restrict__ acoustic, int ML) {
    const int r = blockIdx.x;
    const int b = blockIdx.y;
    const int d = threadIdx.x * 4;

    float4 acc = make_float4(0.f, 0.f, 0.f, 0.f);
    if (r < g_nf[b]) {
        const float* hb = hidden + (size_t)b * NT * ND + d;
        const float2 fc = g_fire[b * NT + r];
        const int end   = __float_as_int(fc.x);
        int start = 0;
        if (r > 0) {
            const float2 fp = g_fire[b * NT + r - 1];
            const int ps    = __float_as_int(fp.x);
            const float rem = fp.y;
            const float4 h  = *reinterpret_cast<const float4*>(hb + (size_t)ps * ND);
            acc.x = rem * h.x; acc.y = rem * h.y;
            acc.z = rem * h.z; acc.w = rem * h.w;
            start = ps + 1;
        }
        for (int t = start; t <= end; t++) {
            const float w  = g_Wt[b * NT + t];   // uniform broadcast load (exact cur)
            const float4 h = *reinterpret_cast<const float4*>(hb + (size_t)t * ND);
            acc.x = fmaf(w, h.x, acc.x); acc.y = fmaf(w, h.y, acc.y);
            acc.z = fmaf(w, h.z, acc.z); acc.w = fmaf(w, h.w, acc.w);
        }
    }
    // r >= nf -> zeros (reference zero-pads); also overwrites 0xAA poison.
    *reinterpret_cast<float4*>(&acoustic[((size_t)b * ML + r) * ND + d]) = acc;
}

// ---------------- launch ----------------------------------------------------
extern "C" void kernel_launch(void* const* d_in, const int* in_sizes, int n_in,
                              void* d_out, int out_size) {
    const float* hidden = (const float*)d_in[0];
    const float* conv_w = (const float*)d_in[1];
    const float* conv_b = (const float*)d_in[2];
    const float* lin_w  = (const float*)d_in[3];
    const float* lin_b  = (const float*)d_in[4];
    float* out = (float*)d_out;

    // out = concat(acoustic[B,ML,D], token_num[B], alphas[B,T], fires[B,T])
    const int ML = (out_size - NB - 2 * NB * NT) / (NB * ND);
    float* acoustic  = out;
    float* token_num = out + (size_t)NB * ML * ND;
    float* alphas    = token_num + NB;
    float* fires     = alphas + NB * NT;

    alphas_kernel<<<dim3(NT / TBLK, NB), 128>>>(hidden, conv_w, conv_b,
                                                lin_w, lin_b, alphas);
    scan_pass1<<<1, 32>>>(token_num);
    scan_pass2<<<NCH, 32>>>(fires);
    if (ML > 0) gather_kernel<<<dim3(ML, NB), ND / 4>>>(hidden, acoustic, ML);
}